// round 16
// baseline (speedup 1.0000x reference)
#include <cuda_runtime.h>
#include <cstdint>

// Fused 2-layer LSTM + FC head. B=16384, T=10, IN=160, H=256.
// CTA = 16 batch rows, 128 threads -> 2 CTAs/SM (smem 109.6KB) to smooth wave
// quantization (1024 half-CTAs over 148 SMs ~ 3.5 rounds vs 4 full waves).
// Weights pre-transposed once per launch into Wprep (device global) in the
// exact smem-tile image the compute loop consumes, streamed with
// double-buffered cp.async.cg. Inner math: packed fma.rn.f32x2,
// 8 rows x 8 gate-cols per thread.

#define BT    16                  // batch rows per CTA
#define ASTR  676                 // A row stride: 160 x | 256 h0 | 256 h1 | pad
#define WTS2  520                 // W tile row stride (16B-aligned: 2080 B)
#define TK    8                   // k rows per tile
#define TILE_FLOATS (TK * WTS2)   // 4160 floats = 16640 B
#define TILE_CHUNKS (TILE_FLOATS / 4)  // 1040 x 16B
#define NTILES 232                // 52+52+64+64 per step
#define NTHR  128

__device__ __align__(16) float Wprep[NTILES * TILE_FLOATS];
__device__ float Bsum[2048];

typedef unsigned long long u64;

__device__ __forceinline__ u64 packdup(float x) {
    u64 r; asm("mov.b64 %0, {%1, %1};" : "=l"(r) : "f"(x)); return r;
}
__device__ __forceinline__ u64 pack2(float x, float y) {
    u64 r; asm("mov.b64 %0, {%1, %2};" : "=l"(r) : "f"(x), "f"(y)); return r;
}
__device__ __forceinline__ float2 unpack2(u64 v) {
    float2 f; asm("mov.b64 {%0, %1}, %2;" : "=f"(f.x), "=f"(f.y) : "l"(v)); return f;
}
__device__ __forceinline__ void fma2(u64& d, u64 a, u64 b) {
    asm("fma.rn.f32x2 %0, %1, %2, %0;" : "+l"(d) : "l"(a), "l"(b));
}
__device__ __forceinline__ float tanh_ap(float x) {
    float y; asm("tanh.approx.f32 %0, %1;" : "=f"(y) : "f"(x)); return y;
}
__device__ __forceinline__ float sigf(float x) {
    return fmaf(0.5f, tanh_ap(0.5f * x), 0.5f);
}
__device__ __forceinline__ float f4c(const float4& v, int c) {
    return c == 0 ? v.x : (c == 1 ? v.y : (c == 2 ? v.z : v.w));
}
__device__ __forceinline__ uint32_t smem_u32(const void* p) {
    uint32_t a;
    asm("{ .reg .u64 t; cvta.to.shared.u64 t, %1; cvt.u32.u64 %0, t; }"
        : "=r"(a) : "l"(p));
    return a;
}

// ---------------- prep kernels (run once per launch) ----------------

__global__ void prep_weights(const float* __restrict__ Wih0,
                             const float* __restrict__ Whh0,
                             const float* __restrict__ Wih1,
                             const float* __restrict__ Whh1) {
    int idx = blockIdx.x * blockDim.x + threadIdx.x;
    if (idx >= NTILES * TK * 512) return;
    int m  = idx & 511;
    int kk = (idx >> 9) & (TK - 1);
    int ti = idx >> 12;              // idx / (TK*512) with TK=8

    int layer, jb, kb;
    if      (ti < 52)  { layer = 0; jb = 0;   kb = ti * TK; }
    else if (ti < 104) { layer = 0; jb = 128; kb = (ti - 52) * TK; }
    else if (ti < 168) { layer = 1; jb = 0;   kb = (ti - 104) * TK; }
    else               { layer = 1; jb = 128; kb = (ti - 168) * TK; }

    int seg = m >> 6, q = seg & 3, chq = seg >> 2;
    int e = m & 63, cgl = e >> 1, j = e & 1;
    int gate = (q & 1) * 2 + j;
    int gcol = gate * 256 + jb + chq * 64 + 2 * cgl + (q >> 1);
    int kglob = kb + kk;

    float v;
    if (layer == 0)
        v = (kglob < 160) ? Wih0[gcol * 160 + kglob]
                          : Whh0[gcol * 256 + (kglob - 160)];
    else
        v = (kglob < 256) ? Wih1[gcol * 256 + kglob]
                          : Whh1[gcol * 256 + (kglob - 256)];
    Wprep[(size_t)ti * TILE_FLOATS + kk * WTS2 + m] = v;
}

__global__ void prep_bias(const float* __restrict__ bih0, const float* __restrict__ bhh0,
                          const float* __restrict__ bih1, const float* __restrict__ bhh1) {
    int i = blockIdx.x * blockDim.x + threadIdx.x;
    if (i < 1024)      Bsum[i] = bih0[i] + bhh0[i];
    else if (i < 2048) Bsum[i] = bih1[i - 1024] + bhh1[i - 1024];
}

// ---------------- main kernel ----------------

__device__ __forceinline__ void issue_tile(uint32_t wtb_u32, int buf, int tile, int tid) {
    const float* src = Wprep + (size_t)tile * TILE_FLOATS;
    uint32_t dst = wtb_u32 + (uint32_t)buf * (TILE_FLOATS * 4);
    #pragma unroll
    for (int c = 0; c < 9; c++) {
        int off = tid + c * NTHR;
        if (off < TILE_CHUNKS) {
            asm volatile("cp.async.cg.shared.global [%0], [%1], 16;"
                :: "r"(dst + (uint32_t)off * 16), "l"(src + off * 4) : "memory");
        }
    }
    asm volatile("cp.async.commit_group;" ::: "memory");
}

// One output-column pass (128 gate-cols x 4 gates) of one LSTM layer.
template<int KTOT, int ABASE>
__device__ __forceinline__ void layer_pass(
    const float* __restrict__ As, float* __restrict__ Cb,
    const float* __restrict__ WtB, uint32_t wtb_u32,
    int bsoff, int jb, int cboff,
    int tid, int rg, int ch, int cg,
    int& next, int& buf, float (&hst)[8][2])
{
    u64 acc[32];
    {
        u64 pq[4];
        #pragma unroll
        for (int q = 0; q < 4; q++) {
            int hc = jb + ch * 64 + 2 * cg + (q >> 1);
            int g0 = ((q & 1) * 2) * 256 + hc;
            pq[q] = pack2(Bsum[bsoff + g0], Bsum[bsoff + g0 + 256]);
        }
        #pragma unroll
        for (int i = 0; i < 8; i++)
            #pragma unroll
            for (int q = 0; q < 4; q++)
                acc[i * 4 + q] = pq[q];
    }

    const float* ab0 = As + (rg * 8) * ASTR + ABASE;
    const float* wb0 = WtB + ch * 256 + 2 * cg;

    for (int kb = 0; kb < KTOT; kb += TK) {
        asm volatile("cp.async.wait_group 0;" ::: "memory");
        __syncthreads();                       // tile[buf] ready; prev compute done
        issue_tile(wtb_u32, buf ^ 1, next, tid);
        next = (next + 1 == NTILES) ? 0 : next + 1;

        const float* wbase = wb0 + buf * TILE_FLOATS;
        const float* ab = ab0 + kb;
        #pragma unroll
        for (int kq = 0; kq < 2; kq++) {
            float4 av[8];
            #pragma unroll
            for (int i = 0; i < 8; i++)
                av[i] = *reinterpret_cast<const float4*>(ab + i * ASTR + kq * 4);
            #pragma unroll
            for (int c = 0; c < 4; c++) {
                const u64* bp = reinterpret_cast<const u64*>(wbase + (kq * 4 + c) * WTS2);
                u64 b0 = bp[0], b1 = bp[32], b2 = bp[64], b3 = bp[96];
                #pragma unroll
                for (int i = 0; i < 8; i++) {
                    u64 ap = packdup(f4c(av[i], c));
                    fma2(acc[i * 4 + 0], ap, b0);
                    fma2(acc[i * 4 + 1], ap, b1);
                    fma2(acc[i * 4 + 2], ap, b2);
                    fma2(acc[i * 4 + 3], ap, b3);
                }
            }
        }
        buf ^= 1;
    }

    // epilogue: activations + cell update (exclusive (row,hcol) ownership)
    #pragma unroll
    for (int i = 0; i < 8; i++) {
        const int r = rg * 8 + i;
        #pragma unroll
        for (int hh = 0; hh < 2; hh++) {
            float2 pif = unpack2(acc[i * 4 + 2 * hh]);      // (i, f)
            float2 pgo = unpack2(acc[i * 4 + 2 * hh + 1]);  // (g, o)
            float iv = sigf(pif.x);
            float fv = sigf(pif.y);
            float gv = tanh_ap(pgo.x);
            float ov = sigf(pgo.y);
            int hcol = jb + ch * 64 + 2 * cg + hh;
            float* cc = Cb + r * 512 + cboff + hcol;
            float c = fv * cc[0] + iv * gv;
            cc[0] = c;
            hst[i][hh] = ov * tanh_ap(c);
        }
    }
}

__global__ void __launch_bounds__(NTHR)
lstm_fused_kernel(
    const float* __restrict__ x,
    const float* __restrict__ Wfc, const float* __restrict__ bfc,
    float* __restrict__ out)
{
    extern __shared__ float sm[];
    float* As  = sm;                        // [16][676]
    float* Cb  = As + BT * ASTR;            // [16][512] c0|c1
    float* WtB = Cb + BT * 512;             // 2 x tile
    float* Fp  = WtB + 2 * TILE_FLOATS;     // [16][2]

    const int tid = threadIdx.x;
    const int wid = tid >> 5;
    const int rg  = wid & 1;                // row group: rows [8rg, 8rg+8)
    const int ch  = wid >> 1;               // column half within 128-col pass
    const int cg  = tid & 31;
    const int rbase = blockIdx.x * BT;
    const uint32_t wtb_u32 = smem_u32(WtB);

    int next = 1, buf = 0;
    issue_tile(wtb_u32, 0, 0, tid);        // prologue prefetch of tile 0

    for (int idx = tid; idx < BT * ASTR; idx += NTHR) As[idx] = 0.0f;
    for (int idx = tid; idx < BT * 512;  idx += NTHR) Cb[idx] = 0.0f;
    __syncthreads();

    float hstA[8][2], hstB[8][2];
    float fcacc[8];
    #pragma unroll
    for (int i = 0; i < 8; i++) fcacc[i] = 0.0f;

    for (int t = 0; t < 10; t++) {
        // stage x_t (coalesced; made visible by first in-loop barrier)
        for (int f = tid; f < BT * 40; f += NTHR) {
            int row = f / 40, c4 = f % 40;
            float4 v = *reinterpret_cast<const float4*>(
                x + (size_t)(rbase + row) * 1600 + t * 160 + c4 * 4);
            *reinterpret_cast<float4*>(As + row * ASTR + c4 * 4) = v;
        }

        // ===== layer 0 (K = 160 x + 256 h0) =====
        layer_pass<416, 0>(As, Cb, WtB, wtb_u32, 0, 0,   0, tid, rg, ch, cg, next, buf, hstA);
        layer_pass<416, 0>(As, Cb, WtB, wtb_u32, 0, 128, 0, tid, rg, ch, cg, next, buf, hstB);
        __syncthreads();   // all done reading old h0
        #pragma unroll
        for (int i = 0; i < 8; i++) {
            int r = rg * 8 + i;
            *reinterpret_cast<float2*>(As + r * ASTR + 160 + ch * 64 + 2 * cg) =
                make_float2(hstA[i][0], hstA[i][1]);
            *reinterpret_cast<float2*>(As + r * ASTR + 160 + 128 + ch * 64 + 2 * cg) =
                make_float2(hstB[i][0], hstB[i][1]);
        }
        __syncthreads();

        // ===== layer 1 (K = 256 h0 + 256 h1) =====
        layer_pass<512, 160>(As, Cb, WtB, wtb_u32, 1024, 0,   256, tid, rg, ch, cg, next, buf, hstA);
        layer_pass<512, 160>(As, Cb, WtB, wtb_u32, 1024, 128, 256, tid, rg, ch, cg, next, buf, hstB);
        __syncthreads();   // all done reading old h1
        {
            float2 w0 = *reinterpret_cast<const float2*>(Wfc + t * 256 + ch * 64 + 2 * cg);
            float2 w1 = *reinterpret_cast<const float2*>(Wfc + t * 256 + 128 + ch * 64 + 2 * cg);
            #pragma unroll
            for (int i = 0; i < 8; i++) {
                int r = rg * 8 + i;
                *reinterpret_cast<float2*>(As + r * ASTR + 416 + ch * 64 + 2 * cg) =
                    make_float2(hstA[i][0], hstA[i][1]);
                *reinterpret_cast<float2*>(As + r * ASTR + 416 + 128 + ch * 64 + 2 * cg) =
                    make_float2(hstB[i][0], hstB[i][1]);
                fcacc[i] += hstA[i][0] * w0.x + hstA[i][1] * w0.y
                          + hstB[i][0] * w1.x + hstB[i][1] * w1.y;
            }
        }
        __syncthreads();
    }

    asm volatile("cp.async.wait_group 0;" ::: "memory");

    #pragma unroll
    for (int i = 0; i < 8; i++) {
        #pragma unroll
        for (int off = 16; off > 0; off >>= 1)
            fcacc[i] += __shfl_xor_sync(0xffffffffu, fcacc[i], off);
    }
    if (cg == 0) {
        #pragma unroll
        for (int i = 0; i < 8; i++)
            Fp[(rg * 8 + i) * 2 + ch] = fcacc[i];
    }
    __syncthreads();
    if (tid < BT) {
        float v = Fp[tid * 2] + Fp[tid * 2 + 1] + bfc[0];
        out[rbase + tid] = sigf(v);
    }
}

extern "C" void kernel_launch(void* const* d_in, const int* in_sizes, int n_in,
                              void* d_out, int out_size) {
    const float* x    = (const float*)d_in[0];
    const float* Wih0 = (const float*)d_in[1];
    const float* Whh0 = (const float*)d_in[2];
    const float* bih0 = (const float*)d_in[3];
    const float* bhh0 = (const float*)d_in[4];
    const float* Wih1 = (const float*)d_in[5];
    const float* Whh1 = (const float*)d_in[6];
    const float* bih1 = (const float*)d_in[7];
    const float* bhh1 = (const float*)d_in[8];
    const float* Wfc  = (const float*)d_in[9];
    const float* bfc  = (const float*)d_in[10];
    float* out = (float*)d_out;

    int B = in_sizes[0] / (10 * 160);
    int grid = B / BT;

    prep_weights<<<(NTILES * TK * 512 + 255) / 256, 256>>>(Wih0, Whh0, Wih1, Whh1);
    prep_bias<<<8, 256>>>(bih0, bhh0, bih1, bhh1);

    size_t shmem = (size_t)(BT * ASTR + BT * 512 + 2 * TILE_FLOATS + 64) * sizeof(float); // 109568 B
    cudaFuncSetAttribute(lstm_fused_kernel,
                         cudaFuncAttributeMaxDynamicSharedMemorySize, (int)shmem);

    lstm_fused_kernel<<<grid, NTHR, shmem>>>(x, Wfc, bfc, out);
}

// round 17
// speedup vs baseline: 1.0005x; 1.0005x over previous
#include <cuda_runtime.h>
#include <cstdint>

// Fused 2-layer LSTM + FC head. B=16384, T=10, IN=160, H=256.
// CTA = 16 batch rows, 128 threads -> 2 CTAs/SM (smem 109.6KB) to smooth wave
// quantization (1024 half-CTAs over 148 SMs ~ 3.5 rounds vs 4 full waves).
// Weights pre-transposed once per launch into Wprep (device global) in the
// exact smem-tile image the compute loop consumes, streamed with
// double-buffered cp.async.cg. Inner math: packed fma.rn.f32x2,
// 8 rows x 8 gate-cols per thread.

#define BT    16                  // batch rows per CTA
#define ASTR  676                 // A row stride: 160 x | 256 h0 | 256 h1 | pad
#define WTS2  520                 // W tile row stride (16B-aligned: 2080 B)
#define TK    8                   // k rows per tile
#define TILE_FLOATS (TK * WTS2)   // 4160 floats = 16640 B
#define TILE_CHUNKS (TILE_FLOATS / 4)  // 1040 x 16B
#define NTILES 232                // 52+52+64+64 per step
#define NTHR  128

__device__ __align__(16) float Wprep[NTILES * TILE_FLOATS];
__device__ float Bsum[2048];

typedef unsigned long long u64;

__device__ __forceinline__ u64 packdup(float x) {
    u64 r; asm("mov.b64 %0, {%1, %1};" : "=l"(r) : "f"(x)); return r;
}
__device__ __forceinline__ u64 pack2(float x, float y) {
    u64 r; asm("mov.b64 %0, {%1, %2};" : "=l"(r) : "f"(x), "f"(y)); return r;
}
__device__ __forceinline__ float2 unpack2(u64 v) {
    float2 f; asm("mov.b64 {%0, %1}, %2;" : "=f"(f.x), "=f"(f.y) : "l"(v)); return f;
}
__device__ __forceinline__ void fma2(u64& d, u64 a, u64 b) {
    asm("fma.rn.f32x2 %0, %1, %2, %0;" : "+l"(d) : "l"(a), "l"(b));
}
__device__ __forceinline__ float tanh_ap(float x) {
    float y; asm("tanh.approx.f32 %0, %1;" : "=f"(y) : "f"(x)); return y;
}
__device__ __forceinline__ float sigf(float x) {
    return fmaf(0.5f, tanh_ap(0.5f * x), 0.5f);
}
__device__ __forceinline__ float f4c(const float4& v, int c) {
    return c == 0 ? v.x : (c == 1 ? v.y : (c == 2 ? v.z : v.w));
}
__device__ __forceinline__ uint32_t smem_u32(const void* p) {
    uint32_t a;
    asm("{ .reg .u64 t; cvta.to.shared.u64 t, %1; cvt.u32.u64 %0, t; }"
        : "=r"(a) : "l"(p));
    return a;
}

// ---------------- prep kernels (run once per launch) ----------------

__global__ void prep_weights(const float* __restrict__ Wih0,
                             const float* __restrict__ Whh0,
                             const float* __restrict__ Wih1,
                             const float* __restrict__ Whh1) {
    int idx = blockIdx.x * blockDim.x + threadIdx.x;
    if (idx >= NTILES * TK * 512) return;
    int m  = idx & 511;
    int kk = (idx >> 9) & (TK - 1);
    int ti = idx >> 12;              // idx / (TK*512) with TK=8

    int layer, jb, kb;
    if      (ti < 52)  { layer = 0; jb = 0;   kb = ti * TK; }
    else if (ti < 104) { layer = 0; jb = 128; kb = (ti - 52) * TK; }
    else if (ti < 168) { layer = 1; jb = 0;   kb = (ti - 104) * TK; }
    else               { layer = 1; jb = 128; kb = (ti - 168) * TK; }

    int seg = m >> 6, q = seg & 3, chq = seg >> 2;
    int e = m & 63, cgl = e >> 1, j = e & 1;
    int gate = (q & 1) * 2 + j;
    int gcol = gate * 256 + jb + chq * 64 + 2 * cgl + (q >> 1);
    int kglob = kb + kk;

    float v;
    if (layer == 0)
        v = (kglob < 160) ? Wih0[gcol * 160 + kglob]
                          : Whh0[gcol * 256 + (kglob - 160)];
    else
        v = (kglob < 256) ? Wih1[gcol * 256 + kglob]
                          : Whh1[gcol * 256 + (kglob - 256)];
    Wprep[(size_t)ti * TILE_FLOATS + kk * WTS2 + m] = v;
}

__global__ void prep_bias(const float* __restrict__ bih0, const float* __restrict__ bhh0,
                          const float* __restrict__ bih1, const float* __restrict__ bhh1) {
    int i = blockIdx.x * blockDim.x + threadIdx.x;
    if (i < 1024)      Bsum[i] = bih0[i] + bhh0[i];
    else if (i < 2048) Bsum[i] = bih1[i - 1024] + bhh1[i - 1024];
}

// ---------------- main kernel ----------------

__device__ __forceinline__ void issue_tile(uint32_t wtb_u32, int buf, int tile, int tid) {
    const float* src = Wprep + (size_t)tile * TILE_FLOATS;
    uint32_t dst = wtb_u32 + (uint32_t)buf * (TILE_FLOATS * 4);
    #pragma unroll
    for (int c = 0; c < 9; c++) {
        int off = tid + c * NTHR;
        if (off < TILE_CHUNKS) {
            asm volatile("cp.async.cg.shared.global [%0], [%1], 16;"
                :: "r"(dst + (uint32_t)off * 16), "l"(src + off * 4) : "memory");
        }
    }
    asm volatile("cp.async.commit_group;" ::: "memory");
}

// One output-column pass (128 gate-cols x 4 gates) of one LSTM layer.
template<int KTOT, int ABASE>
__device__ __forceinline__ void layer_pass(
    const float* __restrict__ As, float* __restrict__ Cb,
    const float* __restrict__ WtB, uint32_t wtb_u32,
    int bsoff, int jb, int cboff,
    int tid, int rg, int ch, int cg,
    int& next, int& buf, float (&hst)[8][2])
{
    u64 acc[32];
    {
        u64 pq[4];
        #pragma unroll
        for (int q = 0; q < 4; q++) {
            int hc = jb + ch * 64 + 2 * cg + (q >> 1);
            int g0 = ((q & 1) * 2) * 256 + hc;
            pq[q] = pack2(Bsum[bsoff + g0], Bsum[bsoff + g0 + 256]);
        }
        #pragma unroll
        for (int i = 0; i < 8; i++)
            #pragma unroll
            for (int q = 0; q < 4; q++)
                acc[i * 4 + q] = pq[q];
    }

    const float* ab0 = As + (rg * 8) * ASTR + ABASE;
    const float* wb0 = WtB + ch * 256 + 2 * cg;

    for (int kb = 0; kb < KTOT; kb += TK) {
        asm volatile("cp.async.wait_group 0;" ::: "memory");
        __syncthreads();                       // tile[buf] ready; prev compute done
        issue_tile(wtb_u32, buf ^ 1, next, tid);
        next = (next + 1 == NTILES) ? 0 : next + 1;

        const float* wbase = wb0 + buf * TILE_FLOATS;
        const float* ab = ab0 + kb;
        #pragma unroll
        for (int kq = 0; kq < 2; kq++) {
            float4 av[8];
            #pragma unroll
            for (int i = 0; i < 8; i++)
                av[i] = *reinterpret_cast<const float4*>(ab + i * ASTR + kq * 4);
            #pragma unroll
            for (int c = 0; c < 4; c++) {
                const u64* bp = reinterpret_cast<const u64*>(wbase + (kq * 4 + c) * WTS2);
                u64 b0 = bp[0], b1 = bp[32], b2 = bp[64], b3 = bp[96];
                #pragma unroll
                for (int i = 0; i < 8; i++) {
                    u64 ap = packdup(f4c(av[i], c));
                    fma2(acc[i * 4 + 0], ap, b0);
                    fma2(acc[i * 4 + 1], ap, b1);
                    fma2(acc[i * 4 + 2], ap, b2);
                    fma2(acc[i * 4 + 3], ap, b3);
                }
            }
        }
        buf ^= 1;
    }

    // epilogue: activations + cell update (exclusive (row,hcol) ownership)
    #pragma unroll
    for (int i = 0; i < 8; i++) {
        const int r = rg * 8 + i;
        #pragma unroll
        for (int hh = 0; hh < 2; hh++) {
            float2 pif = unpack2(acc[i * 4 + 2 * hh]);      // (i, f)
            float2 pgo = unpack2(acc[i * 4 + 2 * hh + 1]);  // (g, o)
            float iv = sigf(pif.x);
            float fv = sigf(pif.y);
            float gv = tanh_ap(pgo.x);
            float ov = sigf(pgo.y);
            int hcol = jb + ch * 64 + 2 * cg + hh;
            float* cc = Cb + r * 512 + cboff + hcol;
            float c = fv * cc[0] + iv * gv;
            cc[0] = c;
            hst[i][hh] = ov * tanh_ap(c);
        }
    }
}

__global__ void __launch_bounds__(NTHR)
lstm_fused_kernel(
    const float* __restrict__ x,
    const float* __restrict__ Wfc, const float* __restrict__ bfc,
    float* __restrict__ out)
{
    extern __shared__ float sm[];
    float* As  = sm;                        // [16][676]
    float* Cb  = As + BT * ASTR;            // [16][512] c0|c1
    float* WtB = Cb + BT * 512;             // 2 x tile
    float* Fp  = WtB + 2 * TILE_FLOATS;     // [16][2]

    const int tid = threadIdx.x;
    const int wid = tid >> 5;
    const int rg  = wid & 1;                // row group: rows [8rg, 8rg+8)
    const int ch  = wid >> 1;               // column half within 128-col pass
    const int cg  = tid & 31;
    const int rbase = blockIdx.x * BT;
    const uint32_t wtb_u32 = smem_u32(WtB);

    int next = 1, buf = 0;
    issue_tile(wtb_u32, 0, 0, tid);        // prologue prefetch of tile 0

    for (int idx = tid; idx < BT * ASTR; idx += NTHR) As[idx] = 0.0f;
    for (int idx = tid; idx < BT * 512;  idx += NTHR) Cb[idx] = 0.0f;
    __syncthreads();

    float hstA[8][2], hstB[8][2];
    float fcacc[8];
    #pragma unroll
    for (int i = 0; i < 8; i++) fcacc[i] = 0.0f;

    for (int t = 0; t < 10; t++) {
        // stage x_t (coalesced; made visible by first in-loop barrier)
        for (int f = tid; f < BT * 40; f += NTHR) {
            int row = f / 40, c4 = f % 40;
            float4 v = *reinterpret_cast<const float4*>(
                x + (size_t)(rbase + row) * 1600 + t * 160 + c4 * 4);
            *reinterpret_cast<float4*>(As + row * ASTR + c4 * 4) = v;
        }

        // ===== layer 0 (K = 160 x + 256 h0) =====
        layer_pass<416, 0>(As, Cb, WtB, wtb_u32, 0, 0,   0, tid, rg, ch, cg, next, buf, hstA);
        layer_pass<416, 0>(As, Cb, WtB, wtb_u32, 0, 128, 0, tid, rg, ch, cg, next, buf, hstB);
        __syncthreads();   // all done reading old h0
        #pragma unroll
        for (int i = 0; i < 8; i++) {
            int r = rg * 8 + i;
            *reinterpret_cast<float2*>(As + r * ASTR + 160 + ch * 64 + 2 * cg) =
                make_float2(hstA[i][0], hstA[i][1]);
            *reinterpret_cast<float2*>(As + r * ASTR + 160 + 128 + ch * 64 + 2 * cg) =
                make_float2(hstB[i][0], hstB[i][1]);
        }
        __syncthreads();

        // ===== layer 1 (K = 256 h0 + 256 h1) =====
        layer_pass<512, 160>(As, Cb, WtB, wtb_u32, 1024, 0,   256, tid, rg, ch, cg, next, buf, hstA);
        layer_pass<512, 160>(As, Cb, WtB, wtb_u32, 1024, 128, 256, tid, rg, ch, cg, next, buf, hstB);
        __syncthreads();   // all done reading old h1
        {
            float2 w0 = *reinterpret_cast<const float2*>(Wfc + t * 256 + ch * 64 + 2 * cg);
            float2 w1 = *reinterpret_cast<const float2*>(Wfc + t * 256 + 128 + ch * 64 + 2 * cg);
            #pragma unroll
            for (int i = 0; i < 8; i++) {
                int r = rg * 8 + i;
                *reinterpret_cast<float2*>(As + r * ASTR + 416 + ch * 64 + 2 * cg) =
                    make_float2(hstA[i][0], hstA[i][1]);
                *reinterpret_cast<float2*>(As + r * ASTR + 416 + 128 + ch * 64 + 2 * cg) =
                    make_float2(hstB[i][0], hstB[i][1]);
                fcacc[i] += hstA[i][0] * w0.x + hstA[i][1] * w0.y
                          + hstB[i][0] * w1.x + hstB[i][1] * w1.y;
            }
        }
        __syncthreads();
    }

    asm volatile("cp.async.wait_group 0;" ::: "memory");

    #pragma unroll
    for (int i = 0; i < 8; i++) {
        #pragma unroll
        for (int off = 16; off > 0; off >>= 1)
            fcacc[i] += __shfl_xor_sync(0xffffffffu, fcacc[i], off);
    }
    if (cg == 0) {
        #pragma unroll
        for (int i = 0; i < 8; i++)
            Fp[(rg * 8 + i) * 2 + ch] = fcacc[i];
    }
    __syncthreads();
    if (tid < BT) {
        float v = Fp[tid * 2] + Fp[tid * 2 + 1] + bfc[0];
        out[rbase + tid] = sigf(v);
    }
}

extern "C" void kernel_launch(void* const* d_in, const int* in_sizes, int n_in,
                              void* d_out, int out_size) {
    const float* x    = (const float*)d_in[0];
    const float* Wih0 = (const float*)d_in[1];
    const float* Whh0 = (const float*)d_in[2];
    const float* bih0 = (const float*)d_in[3];
    const float* bhh0 = (const float*)d_in[4];
    const float* Wih1 = (const float*)d_in[5];
    const float* Whh1 = (const float*)d_in[6];
    const float* bih1 = (const float*)d_in[7];
    const float* bhh1 = (const float*)d_in[8];
    const float* Wfc  = (const float*)d_in[9];
    const float* bfc  = (const float*)d_in[10];
    float* out = (float*)d_out;

    int B = in_sizes[0] / (10 * 160);
    int grid = B / BT;

    prep_weights<<<(NTILES * TK * 512 + 255) / 256, 256>>>(Wih0, Whh0, Wih1, Whh1);
    prep_bias<<<8, 256>>>(bih0, bhh0, bih1, bhh1);

    size_t shmem = (size_t)(BT * ASTR + BT * 512 + 2 * TILE_FLOATS + 64) * sizeof(float); // 109568 B
    cudaFuncSetAttribute(lstm_fused_kernel,
                         cudaFuncAttributeMaxDynamicSharedMemorySize, (int)shmem);

    lstm_fused_kernel<<<grid, NTHR, shmem>>>(x, Wfc, bfc, out);
}